// round 10
// baseline (speedup 1.0000x reference)
#include <cuda_runtime.h>
#include <math.h>

#define B_    16
#define D_    100000
#define M_    128
#define NBIN_ 25
#define G_    37                  // blocks per batch -> 592 total = 4/SM exactly
#define TOTAL_ (B_ * G_)
#define NSLOT_ 27                 // padded: slot j == bin j-1; slots 0 and 26 are trash

// global accumulators — zero at module load; last block re-zeros them each
// run so every graph replay starts from identical state.
__device__ float    g_hla[B_][NBIN_];
__device__ float    g_hll[B_][NBIN_];
__device__ float    g_lsum[B_];
__device__ unsigned g_ticket;

__global__ void __launch_bounds__(256, 4)
qap_fused(const float* __restrict__ qX,
          const float* __restrict__ dXs,
          const int*   __restrict__ labels,
          float*       __restrict__ out) {
    const int b    = blockIdx.y;
    const int tid  = threadIdx.x;
    const int lane = tid & 31;
    const int warp = tid >> 5;
    const int e    = lane & 7;   // float4 slot within row
    const int g    = lane >> 3;  // doc within 4-doc chunk (0..3)

    // per-(warp,doc) private histograms: [warp][doc(4)][arr][NSLOT_]
    __shared__ float s_hist[8 * 4 * 2 * NSLOT_];   // 6.75 KB
    __shared__ float s_wl[8];
    __shared__ int   s_last;

    #pragma unroll
    for (int i = tid; i < 8 * 4 * 2 * NSLOT_; i += 256) s_hist[i] = 0.0f;
    __syncthreads();

    // query slices + 1/|q| via 8-lane group butterfly
    const float4* __restrict__ qf = reinterpret_cast<const float4*>(qX + b * M_);
    const float4 q0 = qf[e], q1 = qf[e + 8], q2 = qf[e + 16], q3 = qf[e + 24];
    float qs = q0.x*q0.x + q0.y*q0.y + q0.z*q0.z + q0.w*q0.w
             + q1.x*q1.x + q1.y*q1.y + q1.z*q1.z + q1.w*q1.w
             + q2.x*q2.x + q2.y*q2.y + q2.z*q2.z + q2.w*q2.w
             + q3.x*q3.x + q3.y*q3.y + q3.z*q3.z + q3.w*q3.w;
    qs += __shfl_xor_sync(0xFFFFFFFFu, qs, 4);
    qs += __shfl_xor_sync(0xFFFFFFFFu, qs, 2);
    qs += __shfl_xor_sync(0xFFFFFFFFu, qs, 1);
    const float inv_qn = rsqrtf(qs);

    const float4* __restrict__ dv = reinterpret_cast<const float4*>(dXs + (size_t)b * D_ * M_);
    const int*    __restrict__ lb = labels + b * D_;

    const int wid    = blockIdx.x * 8 + warp;
    const int stride = G_ * 8 * 4;       // 1184 docs per sweep
    const int role   = e & 3;            // 0: ha[m0], 1: ha[m1], 2: hl[m0], 3: hl[m1]
    const bool actor = (e < 4);
    float* const hbase = s_hist + ((warp * 4 + g) * 2 + (role >> 1)) * NSLOT_
                       + (role & 1) + 1;
    float labcnt = 0.0f;

    // ---------------- depth-2 software-pipelined loop (4 docs/iter) ----------------
    int d0 = wid * 4;                    // first chunk (always < D_)
    // buffer A <- chunk d0
    const float4* rA = dv + (size_t)(d0 + g) * 32;
    float4 A0 = __ldcs(rA + e),      A1 = __ldcs(rA + e + 8);
    float4 A2 = __ldcs(rA + e + 16), A3 = __ldcs(rA + e + 24);
    int labA = lb[d0 + g];
    // buffer B <- chunk d0+stride (clamped)
    {
        const int d1  = d0 + stride;
        const int d1c = (d1 < D_) ? d1 : 0;
        const float4* rB = dv + (size_t)(d1c + g) * 32;
        B0_label:;
    }
    const int d1i  = d0 + stride;
    const int d1c  = (d1i < D_) ? d1i : 0;
    const float4* rB = dv + (size_t)(d1c + g) * 32;
    float4 B0 = __ldcs(rB + e),      B1 = __ldcs(rB + e + 8);
    float4 B2 = __ldcs(rB + e + 16), B3 = __ldcs(rB + e + 24);
    int labB = lb[d1c + g];

    while (true) {
        // ---- phase A: consume buffer A (chunk d0), prefetch chunk d0+2*stride into A
        {
            const int dp  = d0 + 2 * stride;
            const int dpc = (dp < D_) ? dp : 0;
            const float4* rn = dv + (size_t)(dpc + g) * 32;

            float dot = q0.x*A0.x + q0.y*A0.y + q0.z*A0.z + q0.w*A0.w
                      + q1.x*A1.x + q1.y*A1.y + q1.z*A1.z + q1.w*A1.w
                      + q2.x*A2.x + q2.y*A2.y + q2.z*A2.z + q2.w*A2.w
                      + q3.x*A3.x + q3.y*A3.y + q3.z*A3.z + q3.w*A3.w;
            float nr  = A0.x*A0.x + A0.y*A0.y + A0.z*A0.z + A0.w*A0.w
                      + A1.x*A1.x + A1.y*A1.y + A1.z*A1.z + A1.w*A1.w
                      + A2.x*A2.x + A2.y*A2.y + A2.z*A2.z + A2.w*A2.w
                      + A3.x*A3.x + A3.y*A3.y + A3.z*A3.z + A3.w*A3.w;
            A0 = __ldcs(rn + e);      A1 = __ldcs(rn + e + 8);
            A2 = __ldcs(rn + e + 16); A3 = __ldcs(rn + e + 24);
            const int labcur = labA;
            labA = lb[dpc + g];

            dot += __shfl_xor_sync(0xFFFFFFFFu, dot, 4);
            nr  += __shfl_xor_sync(0xFFFFFFFFu, nr,  4);
            dot += __shfl_xor_sync(0xFFFFFFFFu, dot, 2);
            nr  += __shfl_xor_sync(0xFFFFFFFFu, nr,  2);
            dot += __shfl_xor_sync(0xFFFFFFFFu, dot, 1);
            nr  += __shfl_xor_sync(0xFFFFFFFFu, nr,  1);

            const float sim = dot * rsqrtf(nr) * inv_qn;
            const float t   = (1.0f - sim) * 12.0f;
            const float mf  = floorf(t);
            const int   m0  = (int)mf;
            const float fr  = t - mf;
            float w = (role & 1) ? fr : (1.0f - fr);
            if (role & 2) w *= (float)labcur;
            if (actor) hbase[m0] += w;
            if (e == 0) labcnt += (float)labcur;
        }
        d0 += stride;
        if (d0 >= D_) break;

        // ---- phase B: consume buffer B (chunk d0), prefetch chunk d0+2*stride into B
        {
            const int dp  = d0 + 2 * stride;
            const int dpc = (dp < D_) ? dp : 0;
            const float4* rn = dv + (size_t)(dpc + g) * 32;

            float dot = q0.x*B0.x + q0.y*B0.y + q0.z*B0.z + q0.w*B0.w
                      + q1.x*B1.x + q1.y*B1.y + q1.z*B1.z + q1.w*B1.w
                      + q2.x*B2.x + q2.y*B2.y + q2.z*B2.z + q2.w*B2.w
                      + q3.x*B3.x + q3.y*B3.y + q3.z*B3.z + q3.w*B3.w;
            float nr  = B0.x*B0.x + B0.y*B0.y + B0.z*B0.z + B0.w*B0.w
                      + B1.x*B1.x + B1.y*B1.y + B1.z*B1.z + B1.w*B1.w
                      + B2.x*B2.x + B2.y*B2.y + B2.z*B2.z + B2.w*B2.w
                      + B3.x*B3.x + B3.y*B3.y + B3.z*B3.z + B3.w*B3.w;
            B0 = __ldcs(rn + e);      B1 = __ldcs(rn + e + 8);
            B2 = __ldcs(rn + e + 16); B3 = __ldcs(rn + e + 24);
            const int labcur = labB;
            labB = lb[dpc + g];

            dot += __shfl_xor_sync(0xFFFFFFFFu, dot, 4);
            nr  += __shfl_xor_sync(0xFFFFFFFFu, nr,  4);
            dot += __shfl_xor_sync(0xFFFFFFFFu, dot, 2);
            nr  += __shfl_xor_sync(0xFFFFFFFFu, nr,  2);
            dot += __shfl_xor_sync(0xFFFFFFFFu, dot, 1);
            nr  += __shfl_xor_sync(0xFFFFFFFFu, nr,  1);

            const float sim = dot * rsqrtf(nr) * inv_qn;
            const float t   = (1.0f - sim) * 12.0f;
            const float mf  = floorf(t);
            const int   m0  = (int)mf;
            const float fr  = t - mf;
            float w = (role & 1) ? fr : (1.0f - fr);
            if (role & 2) w *= (float)labcur;
            if (actor) hbase[m0] += w;
            if (e == 0) labcnt += (float)labcur;
        }
        d0 += stride;
        if (d0 >= D_) break;
    }

    #pragma unroll
    for (int o = 16; o; o >>= 1) labcnt += __shfl_xor_sync(0xFFFFFFFFu, labcnt, o);
    if (lane == 0) s_wl[warp] = labcnt;
    __syncthreads();

    // merge the 32 private copies (bins at slot n+1) into global accumulators
    for (int idx = tid; idx < 2 * NBIN_; idx += 256) {
        const int arr = idx / NBIN_, n = idx % NBIN_;
        float s = 0.0f;
        #pragma unroll
        for (int c = 0; c < 32; c++)
            s += s_hist[(c * 2 + arr) * NSLOT_ + n + 1];
        if (arr) atomicAdd(&g_hll[b][n], s);
        else     atomicAdd(&g_hla[b][n], s);
    }
    if (tid == 0) {
        float s = 0.0f;
        #pragma unroll
        for (int w = 0; w < 8; w++) s += s_wl[w];
        atomicAdd(&g_lsum[b], s);
    }

    __threadfence();
    __syncthreads();
    if (tid == 0) {
        unsigned prev = atomicAdd(&g_ticket, 1u);
        s_last = (prev == TOTAL_ - 1u);
    }
    __syncthreads();
    if (!s_last) return;

    // ---------------- last block: finalize + reset state ----------------
    __shared__ float f_hl[B_][NBIN_];
    __shared__ float f_ha[B_][NBIN_];
    __shared__ float f_ls[B_];

    for (int idx = tid; idx < B_ * NBIN_; idx += 256) {
        const int bb = idx / NBIN_, n = idx % NBIN_;
        f_hl[bb][n] = __ldcg(&g_hll[bb][n]);
        f_ha[bb][n] = __ldcg(&g_hla[bb][n]);
        g_hll[bb][n] = 0.0f;
        g_hla[bb][n] = 0.0f;
    }
    if (tid < B_) {
        f_ls[tid] = __ldcg(&g_lsum[tid]);
        g_lsum[tid] = 0.0f;
    }
    __syncthreads();

    float apq = 0.0f;
    if (tid < B_) {
        float cl = 0.0f, ca = 0.0f, s = 0.0f;
        const float inv_lab = 1.0f / f_ls[tid];
        #pragma unroll
        for (int n = 0; n < NBIN_; n++) {
            const float vhl = f_hl[tid][n];
            cl += vhl;
            ca += f_ha[tid][n];
            s += (cl / (ca + 1e-16f)) * (vhl * inv_lab);
        }
        apq = s / (float)NBIN_;
    }
    if (tid < 32) {
        #pragma unroll
        for (int o = 16; o; o >>= 1) apq += __shfl_xor_sync(0xFFFFFFFFu, apq, o);
        if (tid == 0) {
            out[0] = apq / (float)B_;
            g_ticket = 0u;
        }
    }
}

extern "C" void kernel_launch(void* const* d_in, const int* in_sizes, int n_in,
                              void* d_out, int out_size) {
    const float* qX     = (const float*)d_in[0];
    const float* dXs    = (const float*)d_in[1];
    const int*   labels = (const int*)d_in[2];
    float*       out    = (float*)d_out;

    qap_fused<<<dim3(G_, B_), 256>>>(qX, dXs, labels, out);
}

// round 11
// speedup vs baseline: 1.1967x; 1.1967x over previous
#include <cuda_runtime.h>
#include <math.h>

#define B_    16
#define D_    100000
#define M_    128
#define NBIN_ 25
#define G_    37                  // blocks per batch -> 592 total = 4/SM exactly
#define TOTAL_ (B_ * G_)
#define NSLOT_ 27                 // padded: slot j == bin j-1; slots 0 and 26 are trash

// global accumulators — zero at module load; last block re-zeros them each
// run so every graph replay starts from identical state.
__device__ float    g_hla[B_][NBIN_];
__device__ float    g_hll[B_][NBIN_];
__device__ float    g_lsum[B_];
__device__ unsigned g_ticket;

__global__ void __launch_bounds__(256, 4)
qap_fused(const float* __restrict__ qX,
          const float* __restrict__ dXs,
          const int*   __restrict__ labels,
          float*       __restrict__ out) {
    const int b    = blockIdx.y;
    const int tid  = threadIdx.x;
    const int lane = tid & 31;
    const int warp = tid >> 5;
    const int e    = lane & 7;   // float4 slot within row
    const int g    = lane >> 3;  // doc within 4-doc chunk (0..3)

    // per-(warp,doc) private histograms: [warp][doc(4)][arr][NSLOT_]
    __shared__ float s_hist[8 * 4 * 2 * NSLOT_];   // 1728 floats = 6.75 KB
    __shared__ float s_wl[8];
    __shared__ int   s_last;

    #pragma unroll
    for (int i = tid; i < 8 * 4 * 2 * NSLOT_; i += 256) s_hist[i] = 0.0f;
    __syncthreads();

    // query slices + 1/|q| via 8-lane group butterfly
    const float4* __restrict__ qf = reinterpret_cast<const float4*>(qX + b * M_);
    const float4 q0 = qf[e], q1 = qf[e + 8], q2 = qf[e + 16], q3 = qf[e + 24];
    float qs = q0.x*q0.x + q0.y*q0.y + q0.z*q0.z + q0.w*q0.w
             + q1.x*q1.x + q1.y*q1.y + q1.z*q1.z + q1.w*q1.w
             + q2.x*q2.x + q2.y*q2.y + q2.z*q2.z + q2.w*q2.w
             + q3.x*q3.x + q3.y*q3.y + q3.z*q3.z + q3.w*q3.w;
    qs += __shfl_xor_sync(0xFFFFFFFFu, qs, 4);
    qs += __shfl_xor_sync(0xFFFFFFFFu, qs, 2);
    qs += __shfl_xor_sync(0xFFFFFFFFu, qs, 1);
    const float inv_qn = rsqrtf(qs);

    const float4* __restrict__ dv = reinterpret_cast<const float4*>(dXs + (size_t)b * D_ * M_);
    const int*    __restrict__ lb = labels + b * D_;

    const int wid     = blockIdx.x * 8 + warp;
    const int stride4 = G_ * 8 * 4;      // 1184 docs per sweep
    const int role    = e & 3;           // 0: ha[m0], 1: ha[m1], 2: hl[m0], 3: hl[m1]
    const bool actor  = (e < 4);         // 4 handler lanes per doc
    float* const hbase = s_hist + ((warp * 4 + g) * 2 + (role >> 1)) * NSLOT_
                       + (role & 1) + 1;
    float labcnt = 0.0f;

    // ---------------- software-pipelined main loop (4 docs/iter) ----------------
    int d0 = wid * 4;                    // < 1184 <= D_, every warp has work
    const float4* rp = dv + (size_t)(d0 + g) * 32;
    float4 c0 = __ldcs(rp + e),      c1 = __ldcs(rp + e + 8);
    float4 c2 = __ldcs(rp + e + 16), c3 = __ldcs(rp + e + 24);
    int    lab = lb[d0 + g];             // uniform within group -> broadcast

    while (d0 < D_) {
        const int dn   = d0 + stride4;
        const int dpre = (dn < D_) ? dn : 0;   // clamped prefetch (in-bounds, unused if done)
        const float4* rn = dv + (size_t)(dpre + g) * 32;

        // consume current regs into sums
        float dot = q0.x*c0.x + q0.y*c0.y + q0.z*c0.z + q0.w*c0.w
                  + q1.x*c1.x + q1.y*c1.y + q1.z*c1.z + q1.w*c1.w
                  + q2.x*c2.x + q2.y*c2.y + q2.z*c2.z + q2.w*c2.w
                  + q3.x*c3.x + q3.y*c3.y + q3.z*c3.z + q3.w*c3.w;
        float nr  = c0.x*c0.x + c0.y*c0.y + c0.z*c0.z + c0.w*c0.w
                  + c1.x*c1.x + c1.y*c1.y + c1.z*c1.z + c1.w*c1.w
                  + c2.x*c2.x + c2.y*c2.y + c2.z*c2.z + c2.w*c2.w
                  + c3.x*c3.x + c3.y*c3.y + c3.z*c3.z + c3.w*c3.w;

        // refill the (now dead) data regs with the next chunk
        c0 = __ldcs(rn + e);      c1 = __ldcs(rn + e + 8);
        c2 = __ldcs(rn + e + 16); c3 = __ldcs(rn + e + 24);
        const int labcur = lab;
        lab = lb[dpre + g];

        // shuffles + epilogue run UNDER the next chunk's DRAM latency
        dot += __shfl_xor_sync(0xFFFFFFFFu, dot, 4);
        nr  += __shfl_xor_sync(0xFFFFFFFFu, nr,  4);
        dot += __shfl_xor_sync(0xFFFFFFFFu, dot, 2);
        nr  += __shfl_xor_sync(0xFFFFFFFFu, nr,  2);
        dot += __shfl_xor_sync(0xFFFFFFFFu, dot, 1);
        nr  += __shfl_xor_sync(0xFFFFFFFFu, nr,  1);

        const float sim = dot * rsqrtf(nr) * inv_qn;    // eps never binds (norms ~11)
        const float t   = (1.0f - sim) * 12.0f;
        const float mf  = floorf(t);
        const int   m0  = (int)mf;                      // in [-1, 24] for any fp edge
        const float fr  = t - mf;
        float w = (role & 1) ? fr : (1.0f - fr);
        if (role & 2) w *= (float)labcur;               // branchless label gate
        if (actor) hbase[m0] += w;                      // LDS+FADD+STS, race-free
        if (e == 0) labcnt += (float)labcur;            // each doc counted once

        d0 = dn;
    }

    #pragma unroll
    for (int o = 16; o; o >>= 1) labcnt += __shfl_xor_sync(0xFFFFFFFFu, labcnt, o);
    if (lane == 0) s_wl[warp] = labcnt;
    __syncthreads();

    // merge the 32 private copies (bins at slot n+1) into global accumulators
    for (int idx = tid; idx < 2 * NBIN_; idx += 256) {
        const int arr = idx / NBIN_, n = idx % NBIN_;
        float s = 0.0f;
        #pragma unroll
        for (int c = 0; c < 32; c++)
            s += s_hist[(c * 2 + arr) * NSLOT_ + n + 1];
        if (arr) atomicAdd(&g_hll[b][n], s);
        else     atomicAdd(&g_hla[b][n], s);
    }
    if (tid == 0) {
        float s = 0.0f;
        #pragma unroll
        for (int w = 0; w < 8; w++) s += s_wl[w];
        atomicAdd(&g_lsum[b], s);
    }

    __threadfence();
    __syncthreads();
    if (tid == 0) {
        unsigned prev = atomicAdd(&g_ticket, 1u);
        s_last = (prev == TOTAL_ - 1u);
    }
    __syncthreads();
    if (!s_last) return;

    // ---------------- last block: finalize + reset state ----------------
    __shared__ float f_hl[B_][NBIN_];
    __shared__ float f_ha[B_][NBIN_];
    __shared__ float f_ls[B_];

    for (int idx = tid; idx < B_ * NBIN_; idx += 256) {
        const int bb = idx / NBIN_, n = idx % NBIN_;
        f_hl[bb][n] = __ldcg(&g_hll[bb][n]);
        f_ha[bb][n] = __ldcg(&g_hla[bb][n]);
        g_hll[bb][n] = 0.0f;
        g_hla[bb][n] = 0.0f;
    }
    if (tid < B_) {
        f_ls[tid] = __ldcg(&g_lsum[tid]);
        g_lsum[tid] = 0.0f;
    }
    __syncthreads();

    float apq = 0.0f;
    if (tid < B_) {
        float cl = 0.0f, ca = 0.0f, s = 0.0f;
        const float inv_lab = 1.0f / f_ls[tid];
        #pragma unroll
        for (int n = 0; n < NBIN_; n++) {
            const float vhl = f_hl[tid][n];
            cl += vhl;
            ca += f_ha[tid][n];
            s += (cl / (ca + 1e-16f)) * (vhl * inv_lab);
        }
        apq = s / (float)NBIN_;
    }
    if (tid < 32) {
        #pragma unroll
        for (int o = 16; o; o >>= 1) apq += __shfl_xor_sync(0xFFFFFFFFu, apq, o);
        if (tid == 0) {
            out[0] = apq / (float)B_;
            g_ticket = 0u;
        }
    }
}

extern "C" void kernel_launch(void* const* d_in, const int* in_sizes, int n_in,
                              void* d_out, int out_size) {
    const float* qX     = (const float*)d_in[0];
    const float* dXs    = (const float*)d_in[1];
    const int*   labels = (const int*)d_in[2];
    float*       out    = (float*)d_out;

    qap_fused<<<dim3(G_, B_), 256>>>(qX, dXs, labels, out);
}

// round 13
// speedup vs baseline: 1.2201x; 1.0195x over previous
#include <cuda_runtime.h>
#include <math.h>

#define B_    16
#define D_    100000
#define M_    128
#define NBIN_ 25
#define G_    27                  // blocks per batch -> 432 total = 3/SM (148 SMs)
#define TOTAL_ (B_ * G_)
#define NSLOT_ 27                 // padded: slot j == bin j-1; slots 0 and 26 are trash

// global accumulators — zero at module load; last block re-zeros them each
// run so every graph replay starts from identical state.
__device__ float    g_hla[B_][NBIN_];
__device__ float    g_hll[B_][NBIN_];
__device__ float    g_lsum[B_];
__device__ unsigned g_ticket;

__global__ void __launch_bounds__(256, 3)
qap_fused(const float* __restrict__ qX,
          const float* __restrict__ dXs,
          const int*   __restrict__ labels,
          float*       __restrict__ out) {
    const int b    = blockIdx.y;
    const int tid  = threadIdx.x;
    const int lane = tid & 31;
    const int warp = tid >> 5;
    const int e    = lane & 7;   // float4 slot within row
    const int g    = lane >> 3;  // doc within quad (0..3)

    // per-(warp,doc) private histograms: [warp][doc(8)][arr][NSLOT_]
    __shared__ float s_hist[8 * 8 * 2 * NSLOT_];   // 13.5 KB
    __shared__ float s_wl[8];
    __shared__ int   s_last;

    #pragma unroll
    for (int i = tid; i < 8 * 8 * 2 * NSLOT_; i += 256) s_hist[i] = 0.0f;
    __syncthreads();

    // query slices + 1/|q| via 8-lane group butterfly
    const float4* __restrict__ qf = reinterpret_cast<const float4*>(qX + b * M_);
    const float4 q0 = qf[e], q1 = qf[e + 8], q2 = qf[e + 16], q3 = qf[e + 24];
    float qs = q0.x*q0.x + q0.y*q0.y + q0.z*q0.z + q0.w*q0.w
             + q1.x*q1.x + q1.y*q1.y + q1.z*q1.z + q1.w*q1.w
             + q2.x*q2.x + q2.y*q2.y + q2.z*q2.z + q2.w*q2.w
             + q3.x*q3.x + q3.y*q3.y + q3.z*q3.z + q3.w*q3.w;
    qs += __shfl_xor_sync(0xFFFFFFFFu, qs, 4);
    qs += __shfl_xor_sync(0xFFFFFFFFu, qs, 2);
    qs += __shfl_xor_sync(0xFFFFFFFFu, qs, 1);
    const float inv_qn = rsqrtf(qs);

    const float4* __restrict__ dv = reinterpret_cast<const float4*>(dXs + (size_t)b * D_ * M_);
    const int*    __restrict__ lb = labels + b * D_;

    const int wid     = blockIdx.x * 8 + warp;
    const int stride8 = G_ * 8 * 8;      // 1728 docs per sweep
    const int docoff  = g + (e & 4);     // this lane's doc within the 8-doc chunk
    const int role    = e & 3;           // 0: ha[m0], 1: ha[m1], 2: hl[m0], 3: hl[m1]
    float* const hbase = s_hist + ((warp * 8 + docoff) * 2 + (role >> 1)) * NSLOT_
                       + (role & 1) + 1;
    float labcnt = 0.0f;

    // ---------------- software-pipelined main loop (8 docs/iter) ----------------
    int d0 = wid * 8;                    // < 1728 <= D_, every warp has work
    const float4* ra = dv + (size_t)(d0 + g) * 32;
    const float4* rb = ra + 4 * 32;
    float4 a0 = __ldcs(ra + e),      a1 = __ldcs(ra + e + 8);
    float4 a2 = __ldcs(ra + e + 16), a3 = __ldcs(ra + e + 24);
    float4 b0 = __ldcs(rb + e),      b1 = __ldcs(rb + e + 8);
    float4 b2 = __ldcs(rb + e + 16), b3 = __ldcs(rb + e + 24);
    int    lab = lb[d0 + docoff];

    while (d0 < D_) {
        const int dn   = d0 + stride8;
        const int dpre = (dn < D_) ? dn : 0;     // clamped prefetch (in-bounds, unused if done)
        const float4* rna = dv + (size_t)(dpre + g) * 32;
        const float4* rnb = rna + 4 * 32;

        // consume a-regs into sums, refill with next chunk's a-data
        float dota = q0.x*a0.x + q0.y*a0.y + q0.z*a0.z + q0.w*a0.w
                   + q1.x*a1.x + q1.y*a1.y + q1.z*a1.z + q1.w*a1.w
                   + q2.x*a2.x + q2.y*a2.y + q2.z*a2.z + q2.w*a2.w
                   + q3.x*a3.x + q3.y*a3.y + q3.z*a3.z + q3.w*a3.w;
        float nra  = a0.x*a0.x + a0.y*a0.y + a0.z*a0.z + a0.w*a0.w
                   + a1.x*a1.x + a1.y*a1.y + a1.z*a1.z + a1.w*a1.w
                   + a2.x*a2.x + a2.y*a2.y + a2.z*a2.z + a2.w*a2.w
                   + a3.x*a3.x + a3.y*a3.y + a3.z*a3.z + a3.w*a3.w;
        a0 = __ldcs(rna + e);      a1 = __ldcs(rna + e + 8);
        a2 = __ldcs(rna + e + 16); a3 = __ldcs(rna + e + 24);

        // consume b-regs, refill with next chunk's b-data
        float dotb = q0.x*b0.x + q0.y*b0.y + q0.z*b0.z + q0.w*b0.w
                   + q1.x*b1.x + q1.y*b1.y + q1.z*b1.z + q1.w*b1.w
                   + q2.x*b2.x + q2.y*b2.y + q2.z*b2.z + q2.w*b2.w
                   + q3.x*b3.x + q3.y*b3.y + q3.z*b3.z + q3.w*b3.w;
        float nrb  = b0.x*b0.x + b0.y*b0.y + b0.z*b0.z + b0.w*b0.w
                   + b1.x*b1.x + b1.y*b1.y + b1.z*b1.z + b1.w*b1.w
                   + b2.x*b2.x + b2.y*b2.y + b2.z*b2.z + b2.w*b2.w
                   + b3.x*b3.x + b3.y*b3.y + b3.z*b3.z + b3.w*b3.w;
        b0 = __ldcs(rnb + e);      b1 = __ldcs(rnb + e + 8);
        b2 = __ldcs(rnb + e + 16); b3 = __ldcs(rnb + e + 24);

        const int labcur = lab;
        lab = lb[dpre + docoff];

        // shuffles + epilogue run UNDER the next chunk's DRAM latency
        #pragma unroll
        for (int o = 4; o; o >>= 1) {
            dota += __shfl_xor_sync(0xFFFFFFFFu, dota, o);
            nra  += __shfl_xor_sync(0xFFFFFFFFu, nra,  o);
            dotb += __shfl_xor_sync(0xFFFFFFFFu, dotb, o);
            nrb  += __shfl_xor_sync(0xFFFFFFFFu, nrb,  o);
        }

        const float dt  = (e < 4) ? dota : dotb;
        const float nr  = (e < 4) ? nra  : nrb;
        const float sim = dt * rsqrtf(nr) * inv_qn;     // eps never binds (norms ~11)
        const float t   = (1.0f - sim) * 12.0f;
        const float mf  = floorf(t);
        const int   m0  = (int)mf;                      // in [-1, 24] for any fp edge
        const float fr  = t - mf;
        float w = (role & 1) ? fr : (1.0f - fr);
        if (role & 2) w *= (float)labcur;               // branchless label gate
        hbase[m0] += w;                                 // LDS+FADD+STS, race-free
        if (role == 0) labcnt += (float)labcur;         // doc counted once (e==0, e==4)

        d0 = dn;
    }

    #pragma unroll
    for (int o = 16; o; o >>= 1) labcnt += __shfl_xor_sync(0xFFFFFFFFu, labcnt, o);
    if (lane == 0) s_wl[warp] = labcnt;
    __syncthreads();

    // merge the 64 private copies (bins at slot n+1) into global accumulators
    for (int idx = tid; idx < 2 * NBIN_; idx += 256) {
        const int arr = idx / NBIN_, n = idx % NBIN_;
        float s = 0.0f;
        #pragma unroll
        for (int c = 0; c < 64; c++)
            s += s_hist[(c * 2 + arr) * NSLOT_ + n + 1];
        if (arr) atomicAdd(&g_hll[b][n], s);
        else     atomicAdd(&g_hla[b][n], s);
    }
    if (tid == 0) {
        float s = 0.0f;
        #pragma unroll
        for (int w = 0; w < 8; w++) s += s_wl[w];
        atomicAdd(&g_lsum[b], s);
    }

    __threadfence();
    __syncthreads();
    if (tid == 0) {
        unsigned prev = atomicAdd(&g_ticket, 1u);
        s_last = (prev == TOTAL_ - 1u);
    }
    __syncthreads();
    if (!s_last) return;

    // ---------------- last block: finalize + reset state ----------------
    __shared__ float f_hl[B_][NBIN_];
    __shared__ float f_ha[B_][NBIN_];
    __shared__ float f_ls[B_];

    for (int idx = tid; idx < B_ * NBIN_; idx += 256) {
        const int bb = idx / NBIN_, n = idx % NBIN_;
        f_hl[bb][n] = __ldcg(&g_hll[bb][n]);
        f_ha[bb][n] = __ldcg(&g_hla[bb][n]);
        g_hll[bb][n] = 0.0f;
        g_hla[bb][n] = 0.0f;
    }
    if (tid < B_) {
        f_ls[tid] = __ldcg(&g_lsum[tid]);
        g_lsum[tid] = 0.0f;
    }
    __syncthreads();

    float apq = 0.0f;
    if (tid < B_) {
        float cl = 0.0f, ca = 0.0f, s = 0.0f;
        const float inv_lab = 1.0f / f_ls[tid];
        #pragma unroll
        for (int n = 0; n < NBIN_; n++) {
            const float vhl = f_hl[tid][n];
            cl += vhl;
            ca += f_ha[tid][n];
            s += (cl / (ca + 1e-16f)) * (vhl * inv_lab);
        }
        apq = s / (float)NBIN_;
    }
    if (tid < 32) {
        #pragma unroll
        for (int o = 16; o; o >>= 1) apq += __shfl_xor_sync(0xFFFFFFFFu, apq, o);
        if (tid == 0) {
            out[0] = apq / (float)B_;
            g_ticket = 0u;
        }
    }
}

extern "C" void kernel_launch(void* const* d_in, const int* in_sizes, int n_in,
                              void* d_out, int out_size) {
    const float* qX     = (const float*)d_in[0];
    const float* dXs    = (const float*)d_in[1];
    const int*   labels = (const int*)d_in[2];
    float*       out    = (float*)d_out;

    qap_fused<<<dim3(G_, B_), 256>>>(qX, dXs, labels, out);
}